// round 1
// baseline (speedup 1.0000x reference)
#include <cuda_runtime.h>
#include <math.h>

#define NN 10000
#define NE 160000
#define HH 128
#define ER 20
#define CUTOFF_F 5.0f
#define PI_F 3.14159265358979323846f

// ---------------- device scratch (static, no allocation) ----------------
__device__ float g_ns [NN*HH];        // node_scalar
__device__ float g_nvA[NN*3*HH];      // node_vector buffer A
__device__ float g_nvB[NN*3*HH];      // node_vector buffer B
__device__ float g_so [NN*3*HH];      // scalar_out (384 per node)
__device__ float g_Uv [NN*3*HH];
__device__ float g_Vv [NN*3*HH];
__device__ float g_rbfc[NE*ER];       // rbf * fcut
__device__ float g_fcut[NE];
__device__ float g_unit[NE*3];
__device__ int   g_deg [NN];
__device__ int   g_off [NN+1];
__device__ int   g_cur [NN];
__device__ int   g_perm[NE];

__device__ __forceinline__ float silu_f(float x){
    return x * (1.0f / (1.0f + __expf(-x)));
}

// ---------------- setup kernels ----------------
__global__ void k_init_ns(const int* __restrict__ z, const float* __restrict__ embed){
    int i = blockIdx.x*blockDim.x + threadIdx.x;
    if (i < NN*HH){ int n = i >> 7; int j = i & 127; g_ns[i] = embed[z[n]*HH + j]; }
}
__global__ void k_zero_nv(){
    int i = blockIdx.x*blockDim.x + threadIdx.x;
    if (i < NN*3*HH) g_nvA[i] = 0.0f;
}
__global__ void k_zero_deg(){
    int i = blockIdx.x*blockDim.x + threadIdx.x;
    if (i < NN) g_deg[i] = 0;
}
__global__ void k_rbf(const float* __restrict__ dist, const float* __restrict__ diff){
    int e = blockIdx.x*blockDim.x + threadIdx.x;
    if (e >= NE) return;
    float d = dist[e];
    float invd = 1.0f / d;
    float fc = (d < CUTOFF_F) ? 0.5f*(cosf(PI_F*d*(1.0f/CUTOFF_F)) + 1.0f) : 0.0f;
    g_fcut[e] = fc;
    float s = fc * invd;
#pragma unroll
    for (int k = 0; k < ER; k++)
        g_rbfc[e*ER + k] = sinf(d * (float)(k+1) * (PI_F/CUTOFF_F)) * s;
#pragma unroll
    for (int dd = 0; dd < 3; dd++) g_unit[e*3 + dd] = diff[e*3 + dd] * invd;
}
__global__ void k_count(const int* __restrict__ edge){
    int e = blockIdx.x*blockDim.x + threadIdx.x;
    if (e < NE) atomicAdd(&g_deg[edge[2*e]], 1);   // dst = edge[:,0]
}
__global__ void k_scan(){
    __shared__ int sm[1024];
    __shared__ int base_s;
    int t = threadIdx.x;
    if (t == 0){ base_s = 0; g_off[0] = 0; }
    __syncthreads();
    for (int c0 = 0; c0 < NN; c0 += 1024){
        int i = c0 + t;
        int v = (i < NN) ? g_deg[i] : 0;
        sm[t] = v;
        __syncthreads();
        for (int ofs = 1; ofs < 1024; ofs <<= 1){
            int tv = (t >= ofs) ? sm[t-ofs] : 0;
            __syncthreads();
            sm[t] += tv;
            __syncthreads();
        }
        int inc = sm[t];
        int b = base_s;
        if (i < NN){ g_off[i+1] = b + inc; g_cur[i] = b + inc - v; }
        __syncthreads();
        if (t == 1023) base_s = b + sm[1023];
        __syncthreads();
    }
}
__global__ void k_scatter(const int* __restrict__ edge){
    int e = blockIdx.x*blockDim.x + threadIdx.x;
    if (e < NE){ int dst = edge[2*e]; int p = atomicAdd(&g_cur[dst], 1); g_perm[p] = e; }
}

// ---------------- per-layer kernels ----------------

// scalar_out = silu(ns@w1+b1)@w2+b2   [NN, 384]
__global__ __launch_bounds__(128) void k_msg_mlp(int l,
        const float* __restrict__ w1_, const float* __restrict__ b1_,
        const float* __restrict__ w2_, const float* __restrict__ b2_){
    const float* w1 = w1_ + l*HH*HH;
    const float* b1 = b1_ + l*HH;
    const float* w2 = w2_ + l*HH*3*HH;
    const float* b2 = b2_ + l*3*HH;
    const int NB = 16;
    __shared__ __align__(16) float As[NB*HH];
    __shared__ __align__(16) float Hs[NB*HH];
    int j = threadIdx.x;
    int n0 = blockIdx.x * NB;
    for (int tdx = j; tdx < NB*HH; tdx += 128) As[tdx] = g_ns[n0*HH + tdx];
    __syncthreads();
    float acc[NB];
#pragma unroll
    for (int i = 0; i < NB; i++) acc[i] = b1[j];
    for (int k = 0; k < HH; k += 4){
        float wa = w1[(k+0)*HH+j], wb = w1[(k+1)*HH+j], wc = w1[(k+2)*HH+j], wd = w1[(k+3)*HH+j];
#pragma unroll
        for (int i = 0; i < NB; i++){
            float4 a = *(const float4*)&As[i*HH + k];
            acc[i] += a.x*wa + a.y*wb + a.z*wc + a.w*wd;
        }
    }
#pragma unroll
    for (int i = 0; i < NB; i++) Hs[i*HH + j] = silu_f(acc[i]);
    __syncthreads();
    for (int g = 0; g < 3; g++){
#pragma unroll
        for (int i = 0; i < NB; i++) acc[i] = b2[g*HH + j];
        for (int k = 0; k < HH; k += 4){
            float wa = w2[(k+0)*3*HH + g*HH + j];
            float wb = w2[(k+1)*3*HH + g*HH + j];
            float wc = w2[(k+2)*3*HH + g*HH + j];
            float wd = w2[(k+3)*3*HH + g*HH + j];
#pragma unroll
            for (int i = 0; i < NB; i++){
                float4 h = *(const float4*)&Hs[i*HH + k];
                acc[i] += h.x*wa + h.y*wb + h.z*wc + h.w*wd;
            }
        }
#pragma unroll
        for (int i = 0; i < NB; i++) g_so[(long)(n0+i)*3*HH + g*HH + j] = acc[i];
    }
}

// gather-based message pass: per dst node accumulate over incoming edges.
__global__ __launch_bounds__(128) void k_edge(int l,
        const int* __restrict__ edge,
        const float* __restrict__ fw_, const float* __restrict__ fb_){
    const float* Wf = fw_ + l*ER*3*HH;
    const float* Bf = fb_ + l*3*HH;
    const float* nv_in  = (l == 1) ? g_nvB : g_nvA;
    float*       nv_out = (l == 1) ? g_nvA : g_nvB;
    int j = threadIdx.x;
    // filter weight columns for this thread, held in registers
    float wf0[ER], wf1[ER], wf2[ER];
#pragma unroll
    for (int k = 0; k < ER; k++){
        wf0[k] = Wf[k*384 + j];
        wf1[k] = Wf[k*384 + 128 + j];
        wf2[k] = Wf[k*384 + 256 + j];
    }
    float bf0 = Bf[j], bf1 = Bf[128+j], bf2 = Bf[256+j];
    const int NPB = 4;
    for (int ni = 0; ni < NPB; ni++){
        int n = blockIdx.x*NPB + ni;
        int s = g_off[n], e1 = g_off[n+1];
        float acc_s = 0.f, av0 = 0.f, av1 = 0.f, av2 = 0.f;
        for (int p = s; p < e1; p++){
            int eid = g_perm[p];
            int src = edge[2*eid + 1];             // src = edge[:,1]
            float fc = g_fcut[eid];
            float f0 = bf0*fc, f1 = bf1*fc, f2 = bf2*fc;
            const float4* r4 = (const float4*)&g_rbfc[eid*ER];
#pragma unroll
            for (int q = 0; q < 5; q++){
                float4 rv = r4[q];
                f0 += rv.x*wf0[4*q] + rv.y*wf0[4*q+1] + rv.z*wf0[4*q+2] + rv.w*wf0[4*q+3];
                f1 += rv.x*wf1[4*q] + rv.y*wf1[4*q+1] + rv.z*wf1[4*q+2] + rv.w*wf1[4*q+3];
                f2 += rv.x*wf2[4*q] + rv.y*wf2[4*q+1] + rv.z*wf2[4*q+2] + rv.w*wf2[4*q+3];
            }
            const float* sb = &g_so[(long)src*384];
            float gsv = f0 * sb[j];
            float gev = f1 * sb[128 + j];
            float ms  = f2 * sb[256 + j];
            acc_s += ms;
            const float* nb = &nv_in[(long)src*384];
            float u0 = g_unit[eid*3], u1 = g_unit[eid*3+1], u2 = g_unit[eid*3+2];
            av0 += nb[j      ]*gsv + gev*u0;
            av1 += nb[128 + j]*gsv + gev*u1;
            av2 += nb[256 + j]*gsv + gev*u2;
        }
        g_ns[n*128 + j] += acc_s;
        nv_out[(long)n*384 + j      ] = nv_in[(long)n*384 + j      ] + av0;
        nv_out[(long)n*384 + 128 + j] = nv_in[(long)n*384 + 128 + j] + av1;
        nv_out[(long)n*384 + 256 + j] = nv_in[(long)n*384 + 256 + j] + av2;
    }
}

// Uv = nv@Uw+Ub ; Vv = nv@Vw+Vb over rows (node,d)
__global__ __launch_bounds__(128) void k_uv(int l,
        const float* __restrict__ wU_, const float* __restrict__ bU_,
        const float* __restrict__ wV_, const float* __restrict__ bV_){
    const float* wU = wU_ + l*HH*HH; const float* bU = bU_ + l*HH;
    const float* wV = wV_ + l*HH*HH; const float* bV = bV_ + l*HH;
    const float* nv = (l == 1) ? g_nvA : g_nvB;    // this layer's post-message buffer
    const int NB = 16;
    __shared__ __align__(16) float As[NB*HH];
    int j = threadIdx.x;
    int r0 = blockIdx.x * NB;                       // rows: NN*3 = 30000
    for (int tdx = j; tdx < NB*HH; tdx += 128) As[tdx] = nv[(long)r0*HH + tdx];
    __syncthreads();
    float aU[NB], aV[NB];
#pragma unroll
    for (int i = 0; i < NB; i++){ aU[i] = bU[j]; aV[i] = bV[j]; }
    for (int k = 0; k < HH; k += 4){
        float ua = wU[(k+0)*HH+j], ub = wU[(k+1)*HH+j], uc = wU[(k+2)*HH+j], ud = wU[(k+3)*HH+j];
        float va = wV[(k+0)*HH+j], vb = wV[(k+1)*HH+j], vc = wV[(k+2)*HH+j], vd = wV[(k+3)*HH+j];
#pragma unroll
        for (int i = 0; i < NB; i++){
            float4 a = *(const float4*)&As[i*HH + k];
            aU[i] += a.x*ua + a.y*ub + a.z*uc + a.w*ud;
            aV[i] += a.x*va + a.y*vb + a.z*vc + a.w*vd;
        }
    }
#pragma unroll
    for (int i = 0; i < NB; i++){
        g_Uv[(long)(r0+i)*HH + j] = aU[i];
        g_Vv[(long)(r0+i)*HH + j] = aV[i];
    }
}

// update MLP + apply
__global__ __launch_bounds__(128) void k_upd(int l,
        const float* __restrict__ w1_, const float* __restrict__ b1_,
        const float* __restrict__ w2_, const float* __restrict__ b2_){
    const float* w1 = w1_ + l*2*HH*HH; const float* b1 = b1_ + l*HH;
    const float* w2 = w2_ + l*HH*3*HH; const float* b2 = b2_ + l*3*HH;
    float* nv = (l == 1) ? g_nvA : g_nvB;
    const int NB = 8;
    __shared__ __align__(16) float Ms[NB*2*HH];
    __shared__ __align__(16) float Hs[NB*HH];
    int j = threadIdx.x;
    int n0 = blockIdx.x * NB;
#pragma unroll
    for (int i = 0; i < NB; i++){
        int n = n0 + i;
        float v0 = g_Vv[(long)n*384 + j];
        float v1 = g_Vv[(long)n*384 + 128 + j];
        float v2 = g_Vv[(long)n*384 + 256 + j];
        Ms[i*256 + j]       = sqrtf(v0*v0 + v1*v1 + v2*v2);
        Ms[i*256 + 128 + j] = g_ns[n*128 + j];
    }
    __syncthreads();
    float acc[NB];
#pragma unroll
    for (int i = 0; i < NB; i++) acc[i] = b1[j];
    for (int k = 0; k < 2*HH; k += 4){
        float wa = w1[(k+0)*HH+j], wb = w1[(k+1)*HH+j], wc = w1[(k+2)*HH+j], wd = w1[(k+3)*HH+j];
#pragma unroll
        for (int i = 0; i < NB; i++){
            float4 a = *(const float4*)&Ms[i*256 + k];
            acc[i] += a.x*wa + a.y*wb + a.z*wc + a.w*wd;
        }
    }
#pragma unroll
    for (int i = 0; i < NB; i++) Hs[i*HH + j] = silu_f(acc[i]);
    __syncthreads();
    float avv[NB], asv[NB], ass[NB];
#pragma unroll
    for (int i = 0; i < NB; i++){ avv[i] = b2[j]; asv[i] = b2[128+j]; ass[i] = b2[256+j]; }
    for (int k = 0; k < HH; k += 4){
        float w0a = w2[(k+0)*384 + j],       w0b = w2[(k+1)*384 + j],       w0c = w2[(k+2)*384 + j],       w0d = w2[(k+3)*384 + j];
        float w1a = w2[(k+0)*384 + 128 + j], w1b = w2[(k+1)*384 + 128 + j], w1c = w2[(k+2)*384 + 128 + j], w1d = w2[(k+3)*384 + 128 + j];
        float w2a = w2[(k+0)*384 + 256 + j], w2b = w2[(k+1)*384 + 256 + j], w2c = w2[(k+2)*384 + 256 + j], w2d = w2[(k+3)*384 + 256 + j];
#pragma unroll
        for (int i = 0; i < NB; i++){
            float4 h = *(const float4*)&Hs[i*HH + k];
            avv[i] += h.x*w0a + h.y*w0b + h.z*w0c + h.w*w0d;
            asv[i] += h.x*w1a + h.y*w1b + h.z*w1c + h.w*w1d;
            ass[i] += h.x*w2a + h.y*w2b + h.z*w2c + h.w*w2d;
        }
    }
#pragma unroll
    for (int i = 0; i < NB; i++){
        int n = n0 + i;
        float U0 = g_Uv[(long)n*384 + j], U1 = g_Uv[(long)n*384 + 128 + j], U2 = g_Uv[(long)n*384 + 256 + j];
        float V0 = g_Vv[(long)n*384 + j], V1 = g_Vv[(long)n*384 + 128 + j], V2 = g_Vv[(long)n*384 + 256 + j];
        float duv = U0*V0 + U1*V1 + U2*V2;
        nv[(long)n*384 + j      ] += avv[i]*U0;
        nv[(long)n*384 + 128 + j] += avv[i]*U1;
        nv[(long)n*384 + 256 + j] += avv[i]*U2;
        g_ns[n*128 + j] += asv[i]*duv + ass[i];
    }
}

// readout: out = silu(ns@w1+b1)@w2+b2   [NN, 128]
__global__ __launch_bounds__(128) void k_readout(
        const float* __restrict__ w1, const float* __restrict__ b1,
        const float* __restrict__ w2, const float* __restrict__ b2,
        float* __restrict__ out){
    const int NB = 16;
    __shared__ __align__(16) float As[NB*HH];
    __shared__ __align__(16) float Hs[NB*HH];
    int j = threadIdx.x;
    int n0 = blockIdx.x * NB;
    for (int tdx = j; tdx < NB*HH; tdx += 128) As[tdx] = g_ns[n0*HH + tdx];
    __syncthreads();
    float acc[NB];
#pragma unroll
    for (int i = 0; i < NB; i++) acc[i] = b1[j];
    for (int k = 0; k < HH; k += 4){
        float wa = w1[(k+0)*HH+j], wb = w1[(k+1)*HH+j], wc = w1[(k+2)*HH+j], wd = w1[(k+3)*HH+j];
#pragma unroll
        for (int i = 0; i < NB; i++){
            float4 a = *(const float4*)&As[i*HH + k];
            acc[i] += a.x*wa + a.y*wb + a.z*wc + a.w*wd;
        }
    }
#pragma unroll
    for (int i = 0; i < NB; i++) Hs[i*HH + j] = silu_f(acc[i]);
    __syncthreads();
#pragma unroll
    for (int i = 0; i < NB; i++) acc[i] = b2[j];
    for (int k = 0; k < HH; k += 4){
        float wa = w2[(k+0)*HH+j], wb = w2[(k+1)*HH+j], wc = w2[(k+2)*HH+j], wd = w2[(k+3)*HH+j];
#pragma unroll
        for (int i = 0; i < NB; i++){
            float4 h = *(const float4*)&Hs[i*HH + k];
            acc[i] += h.x*wa + h.y*wb + h.z*wc + h.w*wd;
        }
    }
#pragma unroll
    for (int i = 0; i < NB; i++) out[(long)(n0+i)*HH + j] = acc[i];
}

// ---------------- launch ----------------
extern "C" void kernel_launch(void* const* d_in, const int* in_sizes, int n_in,
                              void* d_out, int out_size){
    const int*   z         = (const int*)  d_in[0];
    const int*   edge      = (const int*)  d_in[1];
    const float* edge_diff = (const float*)d_in[2];
    const float* edge_dist = (const float*)d_in[3];
    const float* embed     = (const float*)d_in[4];
    const float* mfw = (const float*)d_in[5];
    const float* mfb = (const float*)d_in[6];
    const float* mw1 = (const float*)d_in[7];
    const float* mb1 = (const float*)d_in[8];
    const float* mw2 = (const float*)d_in[9];
    const float* mb2 = (const float*)d_in[10];
    const float* uUw = (const float*)d_in[11];
    const float* uUb = (const float*)d_in[12];
    const float* uVw = (const float*)d_in[13];
    const float* uVb = (const float*)d_in[14];
    const float* uw1 = (const float*)d_in[15];
    const float* ub1 = (const float*)d_in[16];
    const float* uw2 = (const float*)d_in[17];
    const float* ub2 = (const float*)d_in[18];
    const float* rw1 = (const float*)d_in[19];
    const float* rb1 = (const float*)d_in[20];
    const float* rw2 = (const float*)d_in[21];
    const float* rb2 = (const float*)d_in[22];
    float* out = (float*)d_out;

    k_init_ns<<<(NN*HH + 255)/256, 256>>>(z, embed);
    k_zero_nv<<<(NN*3*HH + 255)/256, 256>>>();
    k_zero_deg<<<(NN + 255)/256, 256>>>();
    k_rbf<<<(NE + 255)/256, 256>>>(edge_dist, edge_diff);
    k_count<<<(NE + 255)/256, 256>>>(edge);
    k_scan<<<1, 1024>>>();
    k_scatter<<<(NE + 255)/256, 256>>>(edge);

    for (int l = 0; l < 3; l++){
        k_msg_mlp<<<NN/16, 128>>>(l, mw1, mb1, mw2, mb2);
        k_edge<<<NN/4, 128>>>(l, edge, mfw, mfb);
        k_uv<<<NN*3/16, 128>>>(l, uUw, uUb, uVw, uVb);
        k_upd<<<NN/8, 128>>>(l, uw1, ub1, uw2, ub2);
    }
    k_readout<<<NN/16, 128>>>(rw1, rb1, rw2, rb2, out);
}

// round 2
// speedup vs baseline: 1.0706x; 1.0706x over previous
#include <cuda_runtime.h>
#include <math.h>

#define NN 10000
#define NE 160000
#define HH 128
#define ER 20
#define CUTOFF_F 5.0f
#define PI_F 3.14159265358979323846f

typedef unsigned long long u64;

// ---------------- device scratch (static, no allocation) ----------------
__device__ float g_ns [NN*HH];        // node_scalar
__device__ float g_nvA[NN*3*HH];      // node_vector buffer A
__device__ float g_nvB[NN*3*HH];      // node_vector buffer B
__device__ float g_so [NN*3*HH];      // scalar_out (384 per node)
__device__ float g_Uv [NN*3*HH];
__device__ float g_Vv [NN*3*HH];
__device__ float g_prbfc[NE*ER];      // permuted rbf * fcut / d
__device__ float4 g_pgeo[NE];         // permuted (unit.x, unit.y, unit.z, fcut)
__device__ int   g_psrc[NE];          // permuted src index
__device__ int   g_deg [NN];
__device__ int   g_off [NN+1];
__device__ int   g_cur [NN];
__device__ int   g_perm[NE];

__device__ __forceinline__ float silu_f(float x){
    return x * (1.0f / (1.0f + __expf(-x)));
}
__device__ __forceinline__ u64 f2fma(u64 a, u64 b, u64 c){
    u64 d; asm("fma.rn.f32x2 %0, %1, %2, %3;" : "=l"(d) : "l"(a), "l"(b), "l"(c)); return d;
}
__device__ __forceinline__ u64 f2pack(float lo, float hi){
    u64 d; asm("mov.b64 %0, {%1, %2};" : "=l"(d) : "f"(lo), "f"(hi)); return d;
}
__device__ __forceinline__ float f2sum(u64 a){
    float x, y; asm("mov.b64 {%0, %1}, %2;" : "=f"(x), "=f"(y) : "l"(a)); return x + y;
}

// ---------------- setup kernels ----------------
__global__ void k_init_ns(const int* __restrict__ z, const float* __restrict__ embed){
    int i = blockIdx.x*blockDim.x + threadIdx.x;
    if (i < NN*HH){ int n = i >> 7; int j = i & 127; g_ns[i] = embed[z[n]*HH + j]; }
}
__global__ void k_zero_nv(){
    int i = blockIdx.x*blockDim.x + threadIdx.x;
    if (i < NN*3*HH) g_nvA[i] = 0.0f;
}
__global__ void k_zero_deg(){
    int i = blockIdx.x*blockDim.x + threadIdx.x;
    if (i < NN) g_deg[i] = 0;
}
__global__ void k_count(const int* __restrict__ edge){
    int e = blockIdx.x*blockDim.x + threadIdx.x;
    if (e < NE) atomicAdd(&g_deg[edge[2*e]], 1);   // dst = edge[:,0]
}
__global__ void k_scan(){
    __shared__ int sm[1024];
    __shared__ int base_s;
    int t = threadIdx.x;
    if (t == 0){ base_s = 0; g_off[0] = 0; }
    __syncthreads();
    for (int c0 = 0; c0 < NN; c0 += 1024){
        int i = c0 + t;
        int v = (i < NN) ? g_deg[i] : 0;
        sm[t] = v;
        __syncthreads();
        for (int ofs = 1; ofs < 1024; ofs <<= 1){
            int tv = (t >= ofs) ? sm[t-ofs] : 0;
            __syncthreads();
            sm[t] += tv;
            __syncthreads();
        }
        int inc = sm[t];
        int b = base_s;
        if (i < NN){ g_off[i+1] = b + inc; g_cur[i] = b + inc - v; }
        __syncthreads();
        if (t == 1023) base_s = b + sm[1023];
        __syncthreads();
    }
}
__global__ void k_scatter(const int* __restrict__ edge){
    int e = blockIdx.x*blockDim.x + threadIdx.x;
    if (e < NE){ int dst = edge[2*e]; int p = atomicAdd(&g_cur[dst], 1); g_perm[p] = e; }
}
// build permuted per-position edge streams (once per call)
__global__ void k_geom(const int* __restrict__ edge,
                       const float* __restrict__ dist, const float* __restrict__ diff){
    int p = blockIdx.x*blockDim.x + threadIdx.x;
    if (p >= NE) return;
    int e = g_perm[p];
    g_psrc[p] = edge[2*e + 1];            // src = edge[:,1]
    float d = dist[e];
    float invd = 1.0f / d;
    float fc = (d < CUTOFF_F) ? 0.5f*(cosf(PI_F*d*(1.0f/CUTOFF_F)) + 1.0f) : 0.0f;
    g_pgeo[p] = make_float4(diff[3*e]*invd, diff[3*e+1]*invd, diff[3*e+2]*invd, fc);
    float s = fc * invd;
#pragma unroll
    for (int k = 0; k < ER; k++)
        g_prbfc[p*ER + k] = sinf(d * (float)(k+1) * (PI_F/CUTOFF_F)) * s;
}

// ---------------- per-layer kernels ----------------

// scalar_out = silu(ns@w1+b1)@w2+b2   [NN, 384]
__global__ __launch_bounds__(128) void k_msg_mlp(int l,
        const float* __restrict__ w1_, const float* __restrict__ b1_,
        const float* __restrict__ w2_, const float* __restrict__ b2_){
    const float* w1 = w1_ + l*HH*HH;
    const float* b1 = b1_ + l*HH;
    const float* w2 = w2_ + l*HH*3*HH;
    const float* b2 = b2_ + l*3*HH;
    const int NB = 16;
    __shared__ __align__(16) float As[NB*HH];
    __shared__ __align__(16) float Hs[NB*HH];
    int j = threadIdx.x;
    int n0 = blockIdx.x * NB;
    for (int t = j; t < NB*HH; t += 128) As[t] = g_ns[n0*HH + t];
    __syncthreads();
    u64 acc[NB];
#pragma unroll
    for (int i = 0; i < NB; i++) acc[i] = 0ULL;
    for (int k = 0; k < HH; k += 8){
        float w0 = w1[(k+0)*HH+j], w1v = w1[(k+1)*HH+j], w2v = w1[(k+2)*HH+j], w3 = w1[(k+3)*HH+j];
        float w4 = w1[(k+4)*HH+j], w5 = w1[(k+5)*HH+j], w6 = w1[(k+6)*HH+j], w7 = w1[(k+7)*HH+j];
        u64 p0 = f2pack(w0,w1v), p1 = f2pack(w2v,w3), p2 = f2pack(w4,w5), p3 = f2pack(w6,w7);
#pragma unroll
        for (int i = 0; i < NB; i++){
            ulonglong2 a0 = *(const ulonglong2*)&As[i*HH + k];
            ulonglong2 a1 = *(const ulonglong2*)&As[i*HH + k + 4];
            acc[i] = f2fma(a0.x, p0, acc[i]);
            acc[i] = f2fma(a0.y, p1, acc[i]);
            acc[i] = f2fma(a1.x, p2, acc[i]);
            acc[i] = f2fma(a1.y, p3, acc[i]);
        }
    }
    float bb = b1[j];
#pragma unroll
    for (int i = 0; i < NB; i++) Hs[i*HH + j] = silu_f(f2sum(acc[i]) + bb);
    __syncthreads();
    for (int g = 0; g < 3; g++){
#pragma unroll
        for (int i = 0; i < NB; i++) acc[i] = 0ULL;
        for (int k = 0; k < HH; k += 8){
            const float* wb = w2 + g*HH + j;
            float w0 = wb[(k+0)*384], w1v = wb[(k+1)*384], w2v = wb[(k+2)*384], w3 = wb[(k+3)*384];
            float w4 = wb[(k+4)*384], w5 = wb[(k+5)*384], w6 = wb[(k+6)*384], w7 = wb[(k+7)*384];
            u64 p0 = f2pack(w0,w1v), p1 = f2pack(w2v,w3), p2 = f2pack(w4,w5), p3 = f2pack(w6,w7);
#pragma unroll
            for (int i = 0; i < NB; i++){
                ulonglong2 a0 = *(const ulonglong2*)&Hs[i*HH + k];
                ulonglong2 a1 = *(const ulonglong2*)&Hs[i*HH + k + 4];
                acc[i] = f2fma(a0.x, p0, acc[i]);
                acc[i] = f2fma(a0.y, p1, acc[i]);
                acc[i] = f2fma(a1.x, p2, acc[i]);
                acc[i] = f2fma(a1.y, p3, acc[i]);
            }
        }
        float bo = b2[g*HH + j];
#pragma unroll
        for (int i = 0; i < NB; i++) g_so[(long)(n0+i)*384 + g*HH + j] = f2sum(acc[i]) + bo;
    }
}

// gather-based message pass over permuted streams
__global__ __launch_bounds__(128) void k_edge(int l,
        const float* __restrict__ fw_, const float* __restrict__ fb_){
    const float* Wf = fw_ + l*ER*3*HH;
    const float* Bf = fb_ + l*3*HH;
    const float* nv_in  = (l == 1) ? g_nvB : g_nvA;
    float*       nv_out = (l == 1) ? g_nvA : g_nvB;
    int j = threadIdx.x;
    u64 wf0[ER/2], wf1[ER/2], wf2[ER/2];
#pragma unroll
    for (int k = 0; k < ER/2; k++){
        wf0[k] = f2pack(Wf[(2*k)*384 + j],       Wf[(2*k+1)*384 + j]);
        wf1[k] = f2pack(Wf[(2*k)*384 + 128 + j], Wf[(2*k+1)*384 + 128 + j]);
        wf2[k] = f2pack(Wf[(2*k)*384 + 256 + j], Wf[(2*k+1)*384 + 256 + j]);
    }
    float bf0 = Bf[j], bf1 = Bf[128+j], bf2 = Bf[256+j];
    const int NPB = 4;
    for (int ni = 0; ni < NPB; ni++){
        int n = blockIdx.x*NPB + ni;
        int s = g_off[n], e1 = g_off[n+1];
        float acc_s = 0.f, av0 = 0.f, av1 = 0.f, av2 = 0.f;
        for (int p = s; p < e1; p++){
            int src = g_psrc[p];
            float4 geo = g_pgeo[p];
            float fc = geo.w;
            u64 f0a = f2pack(bf0*fc, 0.f);
            u64 f1a = f2pack(bf1*fc, 0.f);
            u64 f2a = f2pack(bf2*fc, 0.f);
            const float4* r4 = (const float4*)&g_prbfc[p*ER];
#pragma unroll
            for (int q = 0; q < 5; q++){
                float4 rv = r4[q];
                u64 rp0 = f2pack(rv.x, rv.y);
                u64 rp1 = f2pack(rv.z, rv.w);
                f0a = f2fma(rp0, wf0[2*q],   f0a);
                f0a = f2fma(rp1, wf0[2*q+1], f0a);
                f1a = f2fma(rp0, wf1[2*q],   f1a);
                f1a = f2fma(rp1, wf1[2*q+1], f1a);
                f2a = f2fma(rp0, wf2[2*q],   f2a);
                f2a = f2fma(rp1, wf2[2*q+1], f2a);
            }
            const float* sb = &g_so[(long)src*384];
            float gsv = f2sum(f0a) * sb[j];
            float gev = f2sum(f1a) * sb[128 + j];
            float ms  = f2sum(f2a) * sb[256 + j];
            acc_s += ms;
            const float* nb = &nv_in[(long)src*384];
            av0 += nb[j      ]*gsv + gev*geo.x;
            av1 += nb[128 + j]*gsv + gev*geo.y;
            av2 += nb[256 + j]*gsv + gev*geo.z;
        }
        g_ns[n*128 + j] += acc_s;
        nv_out[(long)n*384 + j      ] = nv_in[(long)n*384 + j      ] + av0;
        nv_out[(long)n*384 + 128 + j] = nv_in[(long)n*384 + 128 + j] + av1;
        nv_out[(long)n*384 + 256 + j] = nv_in[(long)n*384 + 256 + j] + av2;
    }
}

// Uv = nv@Uw+Ub ; Vv = nv@Vw+Vb over rows (node,d)
__global__ __launch_bounds__(128) void k_uv(int l,
        const float* __restrict__ wU_, const float* __restrict__ bU_,
        const float* __restrict__ wV_, const float* __restrict__ bV_){
    const float* wU = wU_ + l*HH*HH; const float* bU = bU_ + l*HH;
    const float* wV = wV_ + l*HH*HH; const float* bV = bV_ + l*HH;
    const float* nv = (l == 1) ? g_nvA : g_nvB;
    const int NB = 8;
    __shared__ __align__(16) float As[NB*HH];
    int j = threadIdx.x;
    int r0 = blockIdx.x * NB;                       // rows: NN*3 = 30000
    for (int t = j; t < NB*HH; t += 128) As[t] = nv[(long)r0*HH + t];
    __syncthreads();
    u64 aU[NB], aV[NB];
#pragma unroll
    for (int i = 0; i < NB; i++){ aU[i] = 0ULL; aV[i] = 0ULL; }
    for (int k = 0; k < HH; k += 8){
        float u0 = wU[(k+0)*HH+j], u1 = wU[(k+1)*HH+j], u2 = wU[(k+2)*HH+j], u3 = wU[(k+3)*HH+j];
        float u4 = wU[(k+4)*HH+j], u5 = wU[(k+5)*HH+j], u6 = wU[(k+6)*HH+j], u7 = wU[(k+7)*HH+j];
        float v0 = wV[(k+0)*HH+j], v1 = wV[(k+1)*HH+j], v2 = wV[(k+2)*HH+j], v3 = wV[(k+3)*HH+j];
        float v4 = wV[(k+4)*HH+j], v5 = wV[(k+5)*HH+j], v6 = wV[(k+6)*HH+j], v7 = wV[(k+7)*HH+j];
        u64 pu0 = f2pack(u0,u1), pu1 = f2pack(u2,u3), pu2 = f2pack(u4,u5), pu3 = f2pack(u6,u7);
        u64 pv0 = f2pack(v0,v1), pv1 = f2pack(v2,v3), pv2 = f2pack(v4,v5), pv3 = f2pack(v6,v7);
#pragma unroll
        for (int i = 0; i < NB; i++){
            ulonglong2 a0 = *(const ulonglong2*)&As[i*HH + k];
            ulonglong2 a1 = *(const ulonglong2*)&As[i*HH + k + 4];
            aU[i] = f2fma(a0.x, pu0, aU[i]);
            aV[i] = f2fma(a0.x, pv0, aV[i]);
            aU[i] = f2fma(a0.y, pu1, aU[i]);
            aV[i] = f2fma(a0.y, pv1, aV[i]);
            aU[i] = f2fma(a1.x, pu2, aU[i]);
            aV[i] = f2fma(a1.x, pv2, aV[i]);
            aU[i] = f2fma(a1.y, pu3, aU[i]);
            aV[i] = f2fma(a1.y, pv3, aV[i]);
        }
    }
    float bu = bU[j], bv = bV[j];
#pragma unroll
    for (int i = 0; i < NB; i++){
        g_Uv[(long)(r0+i)*HH + j] = f2sum(aU[i]) + bu;
        g_Vv[(long)(r0+i)*HH + j] = f2sum(aV[i]) + bv;
    }
}

// update MLP + apply
__global__ __launch_bounds__(128) void k_upd(int l,
        const float* __restrict__ w1_, const float* __restrict__ b1_,
        const float* __restrict__ w2_, const float* __restrict__ b2_){
    const float* w1 = w1_ + l*2*HH*HH; const float* b1 = b1_ + l*HH;
    const float* w2 = w2_ + l*HH*3*HH; const float* b2 = b2_ + l*3*HH;
    float* nv = (l == 1) ? g_nvA : g_nvB;
    const int NB = 8;
    __shared__ __align__(16) float Ms[NB*2*HH];
    __shared__ __align__(16) float Hs[NB*HH];
    __shared__ __align__(16) float Os[NB*3*HH];
    int j = threadIdx.x;
    int n0 = blockIdx.x * NB;
#pragma unroll
    for (int i = 0; i < NB; i++){
        int n = n0 + i;
        float v0 = g_Vv[(long)n*384 + j];
        float v1 = g_Vv[(long)n*384 + 128 + j];
        float v2 = g_Vv[(long)n*384 + 256 + j];
        Ms[i*256 + j]       = sqrtf(v0*v0 + v1*v1 + v2*v2);
        Ms[i*256 + 128 + j] = g_ns[n*128 + j];
    }
    __syncthreads();
    u64 acc[NB];
#pragma unroll
    for (int i = 0; i < NB; i++) acc[i] = 0ULL;
    for (int k = 0; k < 2*HH; k += 8){
        float w0 = w1[(k+0)*HH+j], w1v = w1[(k+1)*HH+j], w2v = w1[(k+2)*HH+j], w3 = w1[(k+3)*HH+j];
        float w4 = w1[(k+4)*HH+j], w5 = w1[(k+5)*HH+j], w6 = w1[(k+6)*HH+j], w7 = w1[(k+7)*HH+j];
        u64 p0 = f2pack(w0,w1v), p1 = f2pack(w2v,w3), p2 = f2pack(w4,w5), p3 = f2pack(w6,w7);
#pragma unroll
        for (int i = 0; i < NB; i++){
            ulonglong2 a0 = *(const ulonglong2*)&Ms[i*256 + k];
            ulonglong2 a1 = *(const ulonglong2*)&Ms[i*256 + k + 4];
            acc[i] = f2fma(a0.x, p0, acc[i]);
            acc[i] = f2fma(a0.y, p1, acc[i]);
            acc[i] = f2fma(a1.x, p2, acc[i]);
            acc[i] = f2fma(a1.y, p3, acc[i]);
        }
    }
    float bb = b1[j];
#pragma unroll
    for (int i = 0; i < NB; i++) Hs[i*HH + j] = silu_f(f2sum(acc[i]) + bb);
    __syncthreads();
    for (int g = 0; g < 3; g++){
#pragma unroll
        for (int i = 0; i < NB; i++) acc[i] = 0ULL;
        for (int k = 0; k < HH; k += 8){
            const float* wb = w2 + g*HH + j;
            float w0 = wb[(k+0)*384], w1v = wb[(k+1)*384], w2v = wb[(k+2)*384], w3 = wb[(k+3)*384];
            float w4 = wb[(k+4)*384], w5 = wb[(k+5)*384], w6 = wb[(k+6)*384], w7 = wb[(k+7)*384];
            u64 p0 = f2pack(w0,w1v), p1 = f2pack(w2v,w3), p2 = f2pack(w4,w5), p3 = f2pack(w6,w7);
#pragma unroll
            for (int i = 0; i < NB; i++){
                ulonglong2 a0 = *(const ulonglong2*)&Hs[i*HH + k];
                ulonglong2 a1 = *(const ulonglong2*)&Hs[i*HH + k + 4];
                acc[i] = f2fma(a0.x, p0, acc[i]);
                acc[i] = f2fma(a0.y, p1, acc[i]);
                acc[i] = f2fma(a1.x, p2, acc[i]);
                acc[i] = f2fma(a1.y, p3, acc[i]);
            }
        }
        float bo = b2[g*HH + j];
#pragma unroll
        for (int i = 0; i < NB; i++) Os[i*384 + g*HH + j] = f2sum(acc[i]) + bo;
    }
    __syncthreads();
#pragma unroll
    for (int i = 0; i < NB; i++){
        int n = n0 + i;
        float avv = Os[i*384 + j];
        float asv = Os[i*384 + 128 + j];
        float ass = Os[i*384 + 256 + j];
        float U0 = g_Uv[(long)n*384 + j], U1 = g_Uv[(long)n*384 + 128 + j], U2 = g_Uv[(long)n*384 + 256 + j];
        float V0 = g_Vv[(long)n*384 + j], V1 = g_Vv[(long)n*384 + 128 + j], V2 = g_Vv[(long)n*384 + 256 + j];
        float duv = U0*V0 + U1*V1 + U2*V2;
        nv[(long)n*384 + j      ] += avv*U0;
        nv[(long)n*384 + 128 + j] += avv*U1;
        nv[(long)n*384 + 256 + j] += avv*U2;
        g_ns[n*128 + j] += asv*duv + ass;
    }
}

// readout: out = silu(ns@w1+b1)@w2+b2   [NN, 128]
__global__ __launch_bounds__(128) void k_readout(
        const float* __restrict__ w1, const float* __restrict__ b1,
        const float* __restrict__ w2, const float* __restrict__ b2,
        float* __restrict__ out){
    const int NB = 16;
    __shared__ __align__(16) float As[NB*HH];
    __shared__ __align__(16) float Hs[NB*HH];
    int j = threadIdx.x;
    int n0 = blockIdx.x * NB;
    for (int t = j; t < NB*HH; t += 128) As[t] = g_ns[n0*HH + t];
    __syncthreads();
    u64 acc[NB];
#pragma unroll
    for (int i = 0; i < NB; i++) acc[i] = 0ULL;
    for (int k = 0; k < HH; k += 8){
        float w0 = w1[(k+0)*HH+j], w1v = w1[(k+1)*HH+j], w2v = w1[(k+2)*HH+j], w3 = w1[(k+3)*HH+j];
        float w4 = w1[(k+4)*HH+j], w5 = w1[(k+5)*HH+j], w6 = w1[(k+6)*HH+j], w7 = w1[(k+7)*HH+j];
        u64 p0 = f2pack(w0,w1v), p1 = f2pack(w2v,w3), p2 = f2pack(w4,w5), p3 = f2pack(w6,w7);
#pragma unroll
        for (int i = 0; i < NB; i++){
            ulonglong2 a0 = *(const ulonglong2*)&As[i*HH + k];
            ulonglong2 a1 = *(const ulonglong2*)&As[i*HH + k + 4];
            acc[i] = f2fma(a0.x, p0, acc[i]);
            acc[i] = f2fma(a0.y, p1, acc[i]);
            acc[i] = f2fma(a1.x, p2, acc[i]);
            acc[i] = f2fma(a1.y, p3, acc[i]);
        }
    }
    float bb = b1[j];
#pragma unroll
    for (int i = 0; i < NB; i++) Hs[i*HH + j] = silu_f(f2sum(acc[i]) + bb);
    __syncthreads();
#pragma unroll
    for (int i = 0; i < NB; i++) acc[i] = 0ULL;
    for (int k = 0; k < HH; k += 8){
        float w0 = w2[(k+0)*HH+j], w1v = w2[(k+1)*HH+j], w2v = w2[(k+2)*HH+j], w3 = w2[(k+3)*HH+j];
        float w4 = w2[(k+4)*HH+j], w5 = w2[(k+5)*HH+j], w6 = w2[(k+6)*HH+j], w7 = w2[(k+7)*HH+j];
        u64 p0 = f2pack(w0,w1v), p1 = f2pack(w2v,w3), p2 = f2pack(w4,w5), p3 = f2pack(w6,w7);
#pragma unroll
        for (int i = 0; i < NB; i++){
            ulonglong2 a0 = *(const ulonglong2*)&Hs[i*HH + k];
            ulonglong2 a1 = *(const ulonglong2*)&Hs[i*HH + k + 4];
            acc[i] = f2fma(a0.x, p0, acc[i]);
            acc[i] = f2fma(a0.y, p1, acc[i]);
            acc[i] = f2fma(a1.x, p2, acc[i]);
            acc[i] = f2fma(a1.y, p3, acc[i]);
        }
    }
    float b2v = b2[j];
#pragma unroll
    for (int i = 0; i < NB; i++) out[(long)(n0+i)*HH + j] = f2sum(acc[i]) + b2v;
}

// ---------------- launch ----------------
extern "C" void kernel_launch(void* const* d_in, const int* in_sizes, int n_in,
                              void* d_out, int out_size){
    const int*   z         = (const int*)  d_in[0];
    const int*   edge      = (const int*)  d_in[1];
    const float* edge_diff = (const float*)d_in[2];
    const float* edge_dist = (const float*)d_in[3];
    const float* embed     = (const float*)d_in[4];
    const float* mfw = (const float*)d_in[5];
    const float* mfb = (const float*)d_in[6];
    const float* mw1 = (const float*)d_in[7];
    const float* mb1 = (const float*)d_in[8];
    const float* mw2 = (const float*)d_in[9];
    const float* mb2 = (const float*)d_in[10];
    const float* uUw = (const float*)d_in[11];
    const float* uUb = (const float*)d_in[12];
    const float* uVw = (const float*)d_in[13];
    const float* uVb = (const float*)d_in[14];
    const float* uw1 = (const float*)d_in[15];
    const float* ub1 = (const float*)d_in[16];
    const float* uw2 = (const float*)d_in[17];
    const float* ub2 = (const float*)d_in[18];
    const float* rw1 = (const float*)d_in[19];
    const float* rb1 = (const float*)d_in[20];
    const float* rw2 = (const float*)d_in[21];
    const float* rb2 = (const float*)d_in[22];
    float* out = (float*)d_out;

    k_init_ns<<<(NN*HH + 255)/256, 256>>>(z, embed);
    k_zero_nv<<<(NN*3*HH + 255)/256, 256>>>();
    k_zero_deg<<<(NN + 255)/256, 256>>>();
    k_count<<<(NE + 255)/256, 256>>>(edge);
    k_scan<<<1, 1024>>>();
    k_scatter<<<(NE + 255)/256, 256>>>(edge);
    k_geom<<<(NE + 255)/256, 256>>>(edge, edge_dist, edge_diff);

    for (int l = 0; l < 3; l++){
        k_msg_mlp<<<NN/16, 128>>>(l, mw1, mb1, mw2, mb2);
        k_edge<<<NN/4, 128>>>(l, mfw, mfb);
        k_uv<<<NN*3/8, 128>>>(l, uUw, uUb, uVw, uVb);
        k_upd<<<NN/8, 128>>>(l, uw1, ub1, uw2, ub2);
    }
    k_readout<<<NN/16, 128>>>(rw1, rb1, rw2, rb2, out);
}